// round 5
// baseline (speedup 1.0000x reference)
#include <cuda_runtime.h>
#include <cuda_bf16.h>
#include <math.h>

// Problem constants
#define BQ   4096   // batch
#define SDIM 2048   // state size
#define FDIM 2048   // feature size
#define KDIM 4096   // S + F
#define NDIM 6144   // 3 * S

// ---------------- device scratch (static; no runtime allocation) -------------
__device__ __nv_bfloat16 g_Xhi[(size_t)BQ * KDIM];     // 32 MB
__device__ __nv_bfloat16 g_Xlo[(size_t)BQ * KDIM];     // 32 MB
__device__ __nv_bfloat16 g_WThi[(size_t)NDIM * KDIM];  // 48 MB  (W transposed: [N][K])
__device__ __nv_bfloat16 g_WTlo[(size_t)NDIM * KDIM];  // 48 MB
__device__ float         g_gates[(size_t)BQ * NDIM];   // 96 MB

// ---------------- helpers ----------------------------------------------------
__device__ __forceinline__ void cp16(void* smem, const void* gmem) {
    unsigned sa = (unsigned)__cvta_generic_to_shared(smem);
    asm volatile("cp.async.cg.shared.global [%0], [%1], 16;\n" :: "r"(sa), "l"(gmem));
}
__device__ __forceinline__ void cp_commit() {
    asm volatile("cp.async.commit_group;\n" ::: "memory");
}
__device__ __forceinline__ void cp_wait0() {
    asm volatile("cp.async.wait_group 0;\n" ::: "memory");
}

__device__ __forceinline__ void mma_bf16(float* c, const unsigned* a, const unsigned* b) {
    asm volatile(
        "mma.sync.aligned.m16n8k16.row.col.f32.bf16.bf16.f32 "
        "{%0,%1,%2,%3}, {%4,%5,%6,%7}, {%8,%9}, {%0,%1,%2,%3};\n"
        : "+f"(c[0]), "+f"(c[1]), "+f"(c[2]), "+f"(c[3])
        : "r"(a[0]), "r"(a[1]), "r"(a[2]), "r"(a[3]), "r"(b[0]), "r"(b[1]));
}

// ---------------- kernel 1: build X = [old_h | input], split hi/lo bf16 ------
__global__ void split_x_kernel(const float* __restrict__ old_h,
                               const float* __restrict__ input) {
    size_t i = (size_t)blockIdx.x * 256 + threadIdx.x;   // over BQ*KDIM
    int b = (int)(i >> 12);          // / 4096
    int k = (int)(i & 4095);
    float x = (k < SDIM) ? old_h[(size_t)b * SDIM + k]
                         : input[(size_t)b * FDIM + (k - SDIM)];
    __nv_bfloat16 hi = __float2bfloat16(x);
    g_Xhi[i] = hi;
    g_Xlo[i] = __float2bfloat16(x - __bfloat162float(hi));
}

// ---------------- kernel 2: transpose W [K][N] -> WT [N][K], split hi/lo -----
__global__ void split_wt_kernel(const float* __restrict__ weights) {
    __shared__ float tile[32][33];
    int n0 = blockIdx.x * 32;
    int k0 = blockIdx.y * 32;
    int tx = threadIdx.x;   // 0..31
    int ty = threadIdx.y;   // 0..7
    #pragma unroll
    for (int j = 0; j < 4; j++) {
        int k = ty + j * 8;                      // k-local
        tile[k][tx] = weights[(size_t)(k0 + k) * NDIM + n0 + tx];  // tile[klocal][nlocal]
    }
    __syncthreads();
    #pragma unroll
    for (int j = 0; j < 4; j++) {
        int nl = ty + j * 8;                     // n-local
        float v = tile[tx][nl];                  // = W[k0+tx][n0+nl]
        __nv_bfloat16 hi = __float2bfloat16(v);
        size_t dst = (size_t)(n0 + nl) * KDIM + (k0 + tx);
        g_WThi[dst] = hi;
        g_WTlo[dst] = __float2bfloat16(v - __bfloat162float(hi));
    }
}

// ---------------- kernel 3: GEMM gates = X @ W  (bf16x3, fp32 accum) ---------
// Block tile: 128(M) x 128(N) x 32(K).  8 warps as 2(M) x 4(N); warp = 64x32.
// Effective K = 3*4096 (segments: Xhi*Whi, Xlo*Whi, Xhi*Wlo).
#define SM_STRIDE 40   // 32 + 8 pad: row*20-word stride -> conflict-free frags

__global__ __launch_bounds__(256, 2) void lltm_gemm_kernel() {
    __shared__ __nv_bfloat16 As[2][128 * SM_STRIDE];
    __shared__ __nv_bfloat16 Bs[2][128 * SM_STRIDE];

    const int tid  = threadIdx.x;
    const int warp = tid >> 5, lane = tid & 31;
    const int wm = warp >> 2, wn = warp & 3;       // warp grid 2 x 4
    const int g  = lane >> 2, tig = lane & 3;      // groupID, threadInGroup
    const int m0 = blockIdx.y * 128;
    const int n0 = blockIdx.x * 128;

    // per-thread global-load coordinates (2 x 16B per operand per tile)
    const int lrow = tid >> 2;            // 0..63
    const int lkv  = (tid & 3) * 8;       // 0,8,16,24

    float acc[4][4][4];
    #pragma unroll
    for (int mi = 0; mi < 4; mi++)
        #pragma unroll
        for (int ni = 0; ni < 4; ni++)
            #pragma unroll
            for (int r = 0; r < 4; r++) acc[mi][ni][r] = 0.0f;

    const int NUM_TILES = 3 * (KDIM / 32);   // 384

    auto load_tile = [&](int t, int buf) {
        int seg = t >> 7;                    // 128 k-tiles per segment
        int kk  = (t & 127) << 5;
        const __nv_bfloat16* Ap = (seg == 1) ? g_Xlo  : g_Xhi;
        const __nv_bfloat16* Bp = (seg == 2) ? g_WTlo : g_WThi;
        cp16(&As[buf][lrow        * SM_STRIDE + lkv], Ap + (size_t)(m0 + lrow)      * KDIM + kk + lkv);
        cp16(&As[buf][(lrow + 64) * SM_STRIDE + lkv], Ap + (size_t)(m0 + lrow + 64) * KDIM + kk + lkv);
        cp16(&Bs[buf][lrow        * SM_STRIDE + lkv], Bp + (size_t)(n0 + lrow)      * KDIM + kk + lkv);
        cp16(&Bs[buf][(lrow + 64) * SM_STRIDE + lkv], Bp + (size_t)(n0 + lrow + 64) * KDIM + kk + lkv);
        cp_commit();
    };

    load_tile(0, 0);

    for (int t = 0; t < NUM_TILES; t++) {
        int buf = t & 1;
        cp_wait0();
        __syncthreads();
        if (t + 1 < NUM_TILES) load_tile(t + 1, buf ^ 1);

        const __nv_bfloat16* Asb = As[buf];
        const __nv_bfloat16* Bsb = Bs[buf];

        #pragma unroll
        for (int kh = 0; kh < 32; kh += 16) {
            unsigned af[4][4], bf[4][2];
            #pragma unroll
            for (int mi = 0; mi < 4; mi++) {
                int row = wm * 64 + mi * 16 + g;
                int kc  = kh + 2 * tig;
                af[mi][0] = *(const unsigned*)&Asb[ row      * SM_STRIDE + kc    ];
                af[mi][1] = *(const unsigned*)&Asb[(row + 8) * SM_STRIDE + kc    ];
                af[mi][2] = *(const unsigned*)&Asb[ row      * SM_STRIDE + kc + 8];
                af[mi][3] = *(const unsigned*)&Asb[(row + 8) * SM_STRIDE + kc + 8];
            }
            #pragma unroll
            for (int ni = 0; ni < 4; ni++) {
                int nn = wn * 32 + ni * 8 + g;
                int kc = kh + 2 * tig;
                bf[ni][0] = *(const unsigned*)&Bsb[nn * SM_STRIDE + kc    ];
                bf[ni][1] = *(const unsigned*)&Bsb[nn * SM_STRIDE + kc + 8];
            }
            #pragma unroll
            for (int mi = 0; mi < 4; mi++)
                #pragma unroll
                for (int ni = 0; ni < 4; ni++)
                    mma_bf16(acc[mi][ni], af[mi], bf[ni]);
        }
        // next iteration's top __syncthreads() protects buf from t+2 overwrite
    }

    // store fp32 gate pre-activations
    #pragma unroll
    for (int mi = 0; mi < 4; mi++) {
        #pragma unroll
        for (int ni = 0; ni < 4; ni++) {
            int row = m0 + wm * 64 + mi * 16 + g;
            int col = n0 + wn * 32 + ni * 8 + 2 * tig;
            float2 v0 = make_float2(acc[mi][ni][0], acc[mi][ni][1]);
            float2 v1 = make_float2(acc[mi][ni][2], acc[mi][ni][3]);
            *(float2*)&g_gates[(size_t) row      * NDIM + col] = v0;
            *(float2*)&g_gates[(size_t)(row + 8) * NDIM + col] = v1;
        }
    }
}

// ---------------- kernel 4: fused LLTM epilogue ------------------------------
__global__ void lltm_epilogue_kernel(const float* __restrict__ bias,
                                     const float* __restrict__ old_c,
                                     float* __restrict__ out) {
    size_t i = (size_t)blockIdx.x * 256 + threadIdx.x;   // over BQ*SDIM
    int b = (int)(i >> 11);          // / 2048
    int s = (int)(i & 2047);
    size_t base = (size_t)b * NDIM + s;
    float gi = g_gates[base]            + bias[s];
    float go = g_gates[base + SDIM]     + bias[SDIM + s];
    float gc = g_gates[base + 2 * SDIM] + bias[2 * SDIM + s];
    float ig = 1.0f / (1.0f + expf(-gi));
    float og = 1.0f / (1.0f + expf(-go));
    float cand = (gc > 0.0f) ? gc : expm1f(gc);
    float nc = old_c[i] + cand * ig;
    float nh = tanhf(nc) * og;
    out[i] = nh;                               // new_h
    out[(size_t)BQ * SDIM + i] = nc;           // new_cell
}

// ---------------- launch ------------------------------------------------------
extern "C" void kernel_launch(void* const* d_in, const int* in_sizes, int n_in,
                              void* d_out, int out_size) {
    const float* weights = (const float*)d_in[0];
    const float* bias    = (const float*)d_in[1];
    const float* input   = (const float*)d_in[2];
    const float* old_h   = (const float*)d_in[3];
    const float* old_c   = (const float*)d_in[4];
    float* out = (float*)d_out;
    (void)in_sizes; (void)n_in; (void)out_size;

    // 1. X = [old_h | input], hi/lo bf16 split
    split_x_kernel<<<(BQ * (size_t)KDIM) / 256, 256>>>(old_h, input);

    // 2. W -> WT [N][K], hi/lo split
    {
        dim3 tb(32, 8);
        dim3 tg(NDIM / 32, KDIM / 32);
        split_wt_kernel<<<tg, tb>>>(weights);
    }

    // 3. GEMM (bf16x3)
    {
        dim3 gg(NDIM / 128, BQ / 128);   // (48, 32)
        lltm_gemm_kernel<<<gg, 256>>>();
    }

    // 4. epilogue
    lltm_epilogue_kernel<<<(BQ * (size_t)SDIM) / 256, 256>>>(bias, old_c, out);
}

// round 11
// speedup vs baseline: 1.0598x; 1.0598x over previous
#include <cuda_runtime.h>
#include <cuda_bf16.h>
#include <math.h>

// Problem constants
#define BQ   4096   // batch
#define SDIM 2048   // state size
#define FDIM 2048   // feature size
#define KDIM 4096   // S + F
#define NDIM 6144   // 3 * S

// ---------------- device scratch (static; no runtime allocation) -------------
__device__ __nv_bfloat16 g_Xhi[(size_t)BQ * KDIM];     // 32 MB
__device__ __nv_bfloat16 g_Xlo[(size_t)BQ * KDIM];     // 32 MB
__device__ __nv_bfloat16 g_WThi[(size_t)NDIM * KDIM];  // 48 MB  (W transposed: [N][K])
__device__ __nv_bfloat16 g_WTlo[(size_t)NDIM * KDIM];  // 48 MB
__device__ float         g_gates[(size_t)BQ * NDIM];   // 96 MB

// ---------------- helpers ----------------------------------------------------
__device__ __forceinline__ void cp16(void* smem, const void* gmem) {
    unsigned sa = (unsigned)__cvta_generic_to_shared(smem);
    asm volatile("cp.async.cg.shared.global [%0], [%1], 16;\n" :: "r"(sa), "l"(gmem));
}
__device__ __forceinline__ void cp_commit() {
    asm volatile("cp.async.commit_group;\n" ::: "memory");
}
__device__ __forceinline__ void cp_wait1() {
    asm volatile("cp.async.wait_group 1;\n" ::: "memory");
}

__device__ __forceinline__ void ldmx4(unsigned* r, unsigned addr) {
    asm volatile("ldmatrix.sync.aligned.m8n8.x4.shared.b16 {%0,%1,%2,%3}, [%4];"
                 : "=r"(r[0]), "=r"(r[1]), "=r"(r[2]), "=r"(r[3]) : "r"(addr));
}

__device__ __forceinline__ void mma_bf16(float* c, const unsigned* a,
                                         unsigned b0, unsigned b1) {
    asm volatile(
        "mma.sync.aligned.m16n8k16.row.col.f32.bf16.bf16.f32 "
        "{%0,%1,%2,%3}, {%4,%5,%6,%7}, {%8,%9}, {%0,%1,%2,%3};\n"
        : "+f"(c[0]), "+f"(c[1]), "+f"(c[2]), "+f"(c[3])
        : "r"(a[0]), "r"(a[1]), "r"(a[2]), "r"(a[3]), "r"(b0), "r"(b1));
}

// ---------------- kernel 1: build X = [old_h | input], split hi/lo bf16 ------
__global__ void split_x_kernel(const float* __restrict__ old_h,
                               const float* __restrict__ input) {
    size_t i = (size_t)blockIdx.x * 256 + threadIdx.x;   // over BQ*KDIM
    int b = (int)(i >> 12);
    int k = (int)(i & 4095);
    float x = (k < SDIM) ? old_h[(size_t)b * SDIM + k]
                         : input[(size_t)b * FDIM + (k - SDIM)];
    __nv_bfloat16 hi = __float2bfloat16(x);
    g_Xhi[i] = hi;
    g_Xlo[i] = __float2bfloat16(x - __bfloat162float(hi));
}

// ---------------- kernel 2: transpose W [K][N] -> WT [N][K], split hi/lo -----
__global__ void split_wt_kernel(const float* __restrict__ weights) {
    __shared__ float tile[32][33];
    int n0 = blockIdx.x * 32;
    int k0 = blockIdx.y * 32;
    int tx = threadIdx.x;   // 0..31
    int ty = threadIdx.y;   // 0..7
    #pragma unroll
    for (int j = 0; j < 4; j++) {
        int k = ty + j * 8;
        tile[k][tx] = weights[(size_t)(k0 + k) * NDIM + n0 + tx];
    }
    __syncthreads();
    #pragma unroll
    for (int j = 0; j < 4; j++) {
        int nl = ty + j * 8;
        float v = tile[tx][nl];
        __nv_bfloat16 hi = __float2bfloat16(v);
        size_t dst = (size_t)(n0 + nl) * KDIM + (k0 + tx);
        g_WThi[dst] = hi;
        g_WTlo[dst] = __float2bfloat16(v - __bfloat162float(hi));
    }
}

// ---------------- kernel 3: GEMM gates = X @ W  (bf16x3, fp32 accum) ---------
// CTA tile 128(M) x 256(N), K-stage 64, 3-stage cp.async ring.
// 8 warps as 2(M) x 4(N): warp tile 64 x 64. ldmatrix.x4 fragment loads.
// Row stride 72 bf16 (144 B = 36 words): ldmatrix phases and cp.async writes
// are bank-conflict-free (36*r mod 32 = 4r -> perfect partition).
#define KT 64
#define ROW_STRIDE 72
#define A_STAGE (128 * ROW_STRIDE)     // elems
#define B_STAGE (256 * ROW_STRIDE)
#define GEMM_SMEM ((3 * (A_STAGE + B_STAGE)) * 2)   // 165888 bytes

__global__ __launch_bounds__(256) void lltm_gemm_kernel() {
    extern __shared__ __nv_bfloat16 smem[];
    __nv_bfloat16* As = smem;                 // 3 stages A
    __nv_bfloat16* Bs = smem + 3 * A_STAGE;   // 3 stages B

    const int tid  = threadIdx.x;
    const int warp = tid >> 5, lane = tid & 31;
    const int wm = warp >> 2, wn = warp & 3;       // warp grid 2 x 4
    const int g  = lane >> 2, tig = lane & 3;
    const int m0 = blockIdx.y * 128;
    const int n0 = blockIdx.x * 256;

    float acc[4][8][4];
    #pragma unroll
    for (int mi = 0; mi < 4; mi++)
        #pragma unroll
        for (int ni = 0; ni < 8; ni++)
            #pragma unroll
            for (int r = 0; r < 4; r++) acc[mi][ni][r] = 0.0f;

    const int NUM_STAGES = 3 * (KDIM / KT);   // 192 (3 bf16 correction segments)

    auto load_stage = [&](int t) {
        int seg = t >> 6;                     // 64 stages per segment
        int kk  = (t & 63) << 6;              // *64
        const __nv_bfloat16* Ap = (seg == 1) ? g_Xlo  : g_Xhi;
        const __nv_bfloat16* Bp = (seg == 2) ? g_WTlo : g_WThi;
        int buf = t % 3;
        __nv_bfloat16* Ab = As + buf * A_STAGE;
        __nv_bfloat16* Bb = Bs + buf * B_STAGE;
        #pragma unroll
        for (int i = 0; i < 4; i++) {         // A: 128 rows x 8 chunks of 16B
            int id = tid + i * 256;
            int row = id >> 3;
            int kc = (id & 7) << 3;
            cp16(&Ab[row * ROW_STRIDE + kc], Ap + (size_t)(m0 + row) * KDIM + kk + kc);
        }
        #pragma unroll
        for (int i = 0; i < 8; i++) {         // B: 256 rows x 8 chunks
            int id = tid + i * 256;
            int row = id >> 3;
            int kc = (id & 7) << 3;
            cp16(&Bb[row * ROW_STRIDE + kc], Bp + (size_t)(n0 + row) * KDIM + kk + kc);
        }
        cp_commit();
    };

    load_stage(0);
    load_stage(1);

    // ldmatrix lane addressing: lanes 0-15 -> rows +0..15 at k, 16-31 -> same rows at k+8
    const int lrow = lane & 15;
    const int lkof = (lane >> 4) * 8;

    for (int t = 0; t < NUM_STAGES; t++) {
        cp_wait1();                            // stage t resident (t+1 may be in flight)
        __syncthreads();
        if (t + 2 < NUM_STAGES) load_stage(t + 2);   // reuses stage t-1's buffer

        int buf = t % 3;
        const __nv_bfloat16* Ab = As + buf * A_STAGE;
        const __nv_bfloat16* Bb = Bs + buf * B_STAGE;
        const int arow = wm * 64 + lrow;
        const int brow = wn * 64 + lrow;

        #pragma unroll
        for (int kh = 0; kh < 4; kh++) {
            int k0 = kh * 16 + lkof;
            unsigned af[4][4], bf[4][4];
            #pragma unroll
            for (int mi = 0; mi < 4; mi++)
                ldmx4(af[mi], (unsigned)__cvta_generic_to_shared(
                          &Ab[(arow + mi * 16) * ROW_STRIDE + k0]));
            #pragma unroll
            for (int nj = 0; nj < 4; nj++)
                ldmx4(bf[nj], (unsigned)__cvta_generic_to_shared(
                          &Bb[(brow + nj * 16) * ROW_STRIDE + k0]));
            #pragma unroll
            for (int mi = 0; mi < 4; mi++) {
                #pragma unroll
                for (int nj = 0; nj < 4; nj++) {
                    mma_bf16(acc[mi][2 * nj],     af[mi], bf[nj][0], bf[nj][2]);
                    mma_bf16(acc[mi][2 * nj + 1], af[mi], bf[nj][1], bf[nj][3]);
                }
            }
        }
    }

    // store fp32 gate pre-activations
    #pragma unroll
    for (int mi = 0; mi < 4; mi++) {
        #pragma unroll
        for (int ni = 0; ni < 8; ni++) {
            int row = m0 + wm * 64 + mi * 16 + g;
            int col = n0 + wn * 64 + ni * 8 + 2 * tig;
            *(float2*)&g_gates[(size_t) row      * NDIM + col] =
                make_float2(acc[mi][ni][0], acc[mi][ni][1]);
            *(float2*)&g_gates[(size_t)(row + 8) * NDIM + col] =
                make_float2(acc[mi][ni][2], acc[mi][ni][3]);
        }
    }
}

// ---------------- kernel 4: fused LLTM epilogue (vectorized x4) --------------
__global__ void lltm_epilogue_kernel(const float* __restrict__ bias,
                                     const float* __restrict__ old_c,
                                     float* __restrict__ out) {
    size_t i4 = (size_t)blockIdx.x * 256 + threadIdx.x;  // over BQ*SDIM/4
    size_t i = i4 * 4;
    int b = (int)(i >> 11);
    int s = (int)(i & 2047);
    size_t base = (size_t)b * NDIM + s;

    float4 gi4 = *(const float4*)&g_gates[base];
    float4 go4 = *(const float4*)&g_gates[base + SDIM];
    float4 gc4 = *(const float4*)&g_gates[base + 2 * SDIM];
    float4 bi4 = *(const float4*)&bias[s];
    float4 bo4 = *(const float4*)&bias[SDIM + s];
    float4 bc4 = *(const float4*)&bias[2 * SDIM + s];
    float4 oc4 = *(const float4*)&old_c[i];

    float nh[4], nc[4];
    float gis[4] = {gi4.x + bi4.x, gi4.y + bi4.y, gi4.z + bi4.z, gi4.w + bi4.w};
    float gos[4] = {go4.x + bo4.x, go4.y + bo4.y, go4.z + bo4.z, go4.w + bo4.w};
    float gcs[4] = {gc4.x + bc4.x, gc4.y + bc4.y, gc4.z + bc4.z, gc4.w + bc4.w};
    float ocs[4] = {oc4.x, oc4.y, oc4.z, oc4.w};
    #pragma unroll
    for (int j = 0; j < 4; j++) {
        float ig = 1.0f / (1.0f + __expf(-gis[j]));
        float og = 1.0f / (1.0f + __expf(-gos[j]));
        float cand = (gcs[j] > 0.0f) ? gcs[j] : expm1f(gcs[j]);
        nc[j] = ocs[j] + cand * ig;
        nh[j] = tanhf(nc[j]) * og;
    }
    *(float4*)&out[i] = make_float4(nh[0], nh[1], nh[2], nh[3]);
    *(float4*)&out[(size_t)BQ * SDIM + i] = make_float4(nc[0], nc[1], nc[2], nc[3]);
}

// ---------------- launch ------------------------------------------------------
extern "C" void kernel_launch(void* const* d_in, const int* in_sizes, int n_in,
                              void* d_out, int out_size) {
    const float* weights = (const float*)d_in[0];
    const float* bias    = (const float*)d_in[1];
    const float* input   = (const float*)d_in[2];
    const float* old_h   = (const float*)d_in[3];
    const float* old_c   = (const float*)d_in[4];
    float* out = (float*)d_out;
    (void)in_sizes; (void)n_in; (void)out_size;

    cudaFuncSetAttribute(lltm_gemm_kernel,
                         cudaFuncAttributeMaxDynamicSharedMemorySize, GEMM_SMEM);

    // 1. X = [old_h | input], hi/lo bf16 split
    split_x_kernel<<<(BQ * (size_t)KDIM) / 256, 256>>>(old_h, input);

    // 2. W -> WT [N][K], hi/lo split
    {
        dim3 tb(32, 8);
        dim3 tg(NDIM / 32, KDIM / 32);
        split_wt_kernel<<<tg, tb>>>(weights);
    }

    // 3. GEMM (bf16x3, fp32 accum)
    {
        dim3 gg(NDIM / 256, BQ / 128);   // (24, 32)
        lltm_gemm_kernel<<<gg, 256, GEMM_SMEM>>>();
    }

    // 4. epilogue
    lltm_epilogue_kernel<<<(BQ * (size_t)SDIM) / 1024, 256>>>(bias, old_c, out);
}